// round 13
// baseline (speedup 1.0000x reference)
#include <cuda_runtime.h>
#include <math.h>

#define NPTS 500000
#define DIM  64
#define NC   10000
#define TO   128            // 2*64 combined outputs (q|v)
#define BN_EPS 1e-5f

#define JS 136              // w_s row stride (floats) — swizzled
#define PS 68               // x_s row stride (floats)
#define XSZ (64 * PS)       // floats per x buffer

typedef unsigned long long ull;

// ---------------- scratch ----------------------------------------------------
__device__ float    g_v[(size_t)NPTS * DIM];
__device__ unsigned g_qmax[NC * DIM];
__device__ float    g_qw[NC * DIM];
__device__ float    g_qb[NC];
__device__ float    g_denom[NC];
__device__ float    g_inv[NC];
__device__ float    g_e[NPTS];
__device__ float    g_bnsum[DIM];
__device__ float    g_bnsq[DIM];
__device__ float    g_scale[DIM];
__device__ float    g_shift[DIM];

__device__ __forceinline__ unsigned encf(float f) {
    unsigned u = __float_as_uint(f);
    return (u & 0x80000000u) ? ~u : (u | 0x80000000u);
}
__device__ __forceinline__ float decf(unsigned u) {
    return __uint_as_float((u & 0x80000000u) ? (u & 0x7FFFFFFFu) : ~u);
}
#define ENC_NEG_INF 0x007FFFFFu

// ---------------- packed fp32x2 + cp.async helpers ---------------------------
__device__ __forceinline__ ull pack_dup(float x) {
    ull r;
    asm("mov.b64 %0, {%1, %1};" : "=l"(r) : "f"(x));
    return r;
}
__device__ __forceinline__ void unpack2(ull p, float& lo, float& hi) {
    asm("mov.b64 {%0, %1}, %2;" : "=f"(lo), "=f"(hi) : "l"(p));
}
#define FMA_F32X2(d, a, b, c) \
    asm("fma.rn.f32x2 %0, %1, %2, %3;" : "=l"(d) : "l"(a), "l"(b), "l"(c))

__device__ __forceinline__ unsigned smem_u32(const void* p) {
    unsigned a;
    asm("{ .reg .u64 t; cvta.to.shared.u64 t, %1; cvt.u32.u64 %0, t; }"
        : "=r"(a) : "l"(p));
    return a;
}
#define CP_ASYNC16(dst, src, sz) \
    asm volatile("cp.async.cg.shared.global [%0], [%1], 16, %2;" \
                 :: "r"(dst), "l"(src), "r"(sz) : "memory")
#define CP_COMMIT() asm volatile("cp.async.commit_group;" ::: "memory")
#define CP_WAIT1()  asm volatile("cp.async.wait_group 1;" ::: "memory")

// w_s column swizzle: conflict-free weight loads (16 distinct bank pairs)
__device__ __forceinline__ int jsw(int j) { return j + ((j >> 5) << 1); }

// ---------------- init kernels -----------------------------------------------
__global__ void k_init_qmax() {
    int i = blockIdx.x * blockDim.x + threadIdx.x;
    if (i < NC * DIM) g_qmax[i] = ENC_NEG_INF;
}
__global__ void k_init_denom() {
    int i = blockIdx.x * blockDim.x + threadIdx.x;
    if (i < NC) g_denom[i] = 0.f;
}
__global__ void k_init_bn() {
    int i = threadIdx.x;
    if (i < DIM) { g_bnsum[i] = 0.f; g_bnsq[i] = 0.f; }
}

// ---------------- K1: QV GEMM, cp.async double-buffered x --------------------
// 128 thr; block tile 64 pts x 128 outs; thread tile 8 pts x 8 cols.
// Point ownership interleaved (p = ty + 8*pp) so warp ty-pairs read adjacent
// x_s rows -> disjoint banks -> 1 wavefront per LDS.128.
__global__ __launch_bounds__(128, 3)
void k_qv(const float* __restrict__ x, const int* __restrict__ cluster,
          const float* __restrict__ Wv, const float* __restrict__ bv,
          const float* __restrict__ Wq, const float* __restrict__ bq) {
    extern __shared__ float sm[];
    float* w_s = sm;                    // [64][JS] swizzled
    float* b_s = sm + 64 * JS;          // [128]
    float* x_s = b_s + TO;              // [2][64][PS]
    const unsigned xs32 = smem_u32(x_s);

    const int tid = threadIdx.x;
    const int tx  = tid & 15;
    const int ty  = tid >> 4;           // 0..7; point p = ty + 8*pp
    const int j0  = tx * 8;
    const int jofs = j0 + ((tx >> 2) << 1);

    // weights transposed + biases
    for (int l = tid; l < TO * 16; l += 128) {
        int j = l >> 4, dc = l & 15;
        const float* Wsrc = (j < 64) ? Wq : Wv;
        int jr = j & 63;
        float4 wv = *(const float4*)&Wsrc[jr * 64 + dc * 4];
        int js = jsw(j);
        w_s[(dc * 4 + 0) * JS + js] = wv.x;
        w_s[(dc * 4 + 1) * JS + js] = wv.y;
        w_s[(dc * 4 + 2) * JS + js] = wv.z;
        w_s[(dc * 4 + 3) * JS + js] = wv.w;
    }
    for (int l = tid; l < TO; l += 128)
        b_s[l] = (l < 64) ? bq[l] : bv[l - 64];

    const int numTiles = (NPTS + 63) / 64;

    // stage tile -> x buffer `bsel` via cp.async (8 x 16B per thread)
    auto stage = [&](int tile, int bsel) {
        const int base = tile * 64;
        #pragma unroll
        for (int k = 0; k < 8; k++) {
            int idx = tid + 128 * k;          // 0..1023 float4 slots
            int row = idx >> 4, col = idx & 15;
            int gr  = base + row;
            unsigned sz = (gr < NPTS) ? 16u : 0u;
            const float* src = x + (size_t)(gr < NPTS ? gr : 0) * 64 + col * 4;
            unsigned dst = xs32 + (unsigned)(bsel * XSZ + row * PS + col * 4) * 4u;
            CP_ASYNC16(dst, src, sz);
        }
    };

    int tile = blockIdx.x;
    int buf = 0;
    if (tile < numTiles) stage(tile, 0);
    CP_COMMIT();
    __syncthreads();        // also covers w_s/b_s population

    for (; tile < numTiles; tile += gridDim.x, buf ^= 1) {
        const int base = tile * 64;
        const int nt = tile + gridDim.x;
        if (nt < numTiles) stage(nt, buf ^ 1);
        CP_COMMIT();
        CP_WAIT1();          // current tile's staging complete
        __syncthreads();

        const float* xb = x_s + buf * XSZ;

        ull acc[8][4];
        {
            const ull* bp = (const ull*)&b_s[j0];
            #pragma unroll
            for (int m = 0; m < 4; m++) {
                ull bb = bp[m];
                #pragma unroll
                for (int pp = 0; pp < 8; pp++) acc[pp][m] = bb;
            }
        }

        #pragma unroll 4
        for (int d4 = 0; d4 < 16; d4++) {
            float xr[8][4];
            #pragma unroll
            for (int pp = 0; pp < 8; pp++) {
                float4 t = *(const float4*)&xb[(ty + 8 * pp) * PS + d4 * 4];
                xr[pp][0] = t.x; xr[pp][1] = t.y; xr[pp][2] = t.z; xr[pp][3] = t.w;
            }
            #pragma unroll
            for (int q = 0; q < 4; q++) {
                const int d = d4 * 4 + q;
                const ull* wp = (const ull*)&w_s[d * JS + jofs];
                ull wr[4];
                #pragma unroll
                for (int m = 0; m < 4; m++) wr[m] = wp[m];
                #pragma unroll
                for (int pp = 0; pp < 8; pp++) {
                    ull a = pack_dup(xr[pp][q]);
                    #pragma unroll
                    for (int m = 0; m < 4; m++)
                        FMA_F32X2(acc[pp][m], a, wr[m], acc[pp][m]);
                }
            }
        }

        if (tx < 8) {
            // q: filtered segment max (monotone => precheck race-safe)
            #pragma unroll
            for (int pp = 0; pp < 8; pp++) {
                const int p = ty + 8 * pp;
                if (base + p < NPTS) {
                    const int cl = __ldg(&cluster[base + p]);
                    const uint4* gp = (const uint4*)&g_qmax[cl * 64 + j0];
                    uint4 c0 = __ldg(gp);
                    uint4 c1 = __ldg(gp + 1);
                    unsigned cur[8] = {c0.x, c0.y, c0.z, c0.w,
                                       c1.x, c1.y, c1.z, c1.w};
                    #pragma unroll
                    for (int m = 0; m < 4; m++) {
                        float lo, hi;
                        unpack2(acc[pp][m], lo, hi);
                        unsigned elo = encf(lo), ehi = encf(hi);
                        if (elo > cur[2 * m])
                            atomicMax(&g_qmax[cl * 64 + j0 + 2 * m], elo);
                        if (ehi > cur[2 * m + 1])
                            atomicMax(&g_qmax[cl * 64 + j0 + 2 * m + 1], ehi);
                    }
                }
            }
        } else {
            // v: direct float4 stores
            const int jv = j0 - 64;
            #pragma unroll
            for (int pp = 0; pp < 8; pp++) {
                const int p = ty + 8 * pp;
                if (base + p < NPTS) {
                    float a0, a1, a2, a3, a4, a5, a6, a7;
                    unpack2(acc[pp][0], a0, a1);
                    unpack2(acc[pp][1], a2, a3);
                    unpack2(acc[pp][2], a4, a5);
                    unpack2(acc[pp][3], a6, a7);
                    float* dst = &g_v[(size_t)(base + p) * 64 + jv];
                    *(float4*)dst       = make_float4(a0, a1, a2, a3);
                    *(float4*)(dst + 4) = make_float4(a4, a5, a6, a7);
                }
            }
        }
        __syncthreads();     // everyone done with x_s[buf] before re-staging it
    }
}

// ---------------- K2: qw[c] = Wk^T q[c], qb = q.bk ---------------------------
__global__ __launch_bounds__(256)
void k_qtrans(const float* __restrict__ Wk, const float* __restrict__ bk) {
    __shared__ float wks[64 * 64];
    __shared__ float qs[4][64];
    __shared__ float bks[64];
    const int tid = threadIdx.x;
    for (int l = tid; l < 64 * 64; l += 256) wks[l] = Wk[l];
    if (tid < 64) bks[tid] = bk[tid];
    const int cl = tid >> 6;
    const int d  = tid & 63;
    const int c  = blockIdx.x * 4 + cl;
    qs[cl][d] = decf(g_qmax[c * 64 + d]);
    __syncthreads();
    float s = 0.f;
    #pragma unroll 8
    for (int j = 0; j < 64; j++)
        s = fmaf(qs[cl][j], wks[j * 64 + d], s);
    g_qw[c * 64 + d] = s;
    if (d == 0) {
        float t = 0.f;
        #pragma unroll 8
        for (int j = 0; j < 64; j++) t = fmaf(qs[cl][j], bks[j], t);
        g_qb[c] = t;
    }
}

// ---------------- K3: fused score + exp + denom ------------------------------
__global__ void k_score(const float* __restrict__ x,
                        const int* __restrict__ cluster) {
    int t = blockIdx.x * blockDim.x + threadIdx.x;
    int i = t >> 3;
    int r = t & 7;
    if (i >= NPTS) return;
    int cl = cluster[i];
    const float4* xp = (const float4*)&x[(size_t)i * 64];
    const float4* qp = (const float4*)&g_qw[cl * 64];
    float s = 0.f;
    #pragma unroll
    for (int h = 0; h < 2; h++) {
        float4 xv = xp[r + h * 8];
        float4 qv = qp[r + h * 8];
        s += xv.x * qv.x + xv.y * qv.y + xv.z * qv.z + xv.w * qv.w;
    }
    s += __shfl_down_sync(0xFFFFFFFFu, s, 4);
    s += __shfl_down_sync(0xFFFFFFFFu, s, 2);
    s += __shfl_down_sync(0xFFFFFFFFu, s, 1);
    if (r == 0) {
        float e = expf(s + g_qb[cl]);
        g_e[i] = e;
        atomicAdd(&g_denom[cl], e);
    }
}

// ---------------- K4: inv --------------------------------------------------- 
__global__ void k_invdenom() {
    int c = blockIdx.x * blockDim.x + threadIdx.x;
    if (c < NC) g_inv[c] = 1.0f / g_denom[c];
}

// ---------------- K5: BN statistics ------------------------------------------
__global__ void k_bnstats(const int* __restrict__ cluster) {
    const int tid = threadIdx.x;
    const int jj  = tid & 63;
    const int pg  = tid >> 6;
    float s = 0.f, s2 = 0.f;
    for (int i = blockIdx.x * 4 + pg; i < NPTS; i += gridDim.x * 4) {
        float attn = g_e[i] * g_inv[cluster[i]];
        float h = attn * g_v[(size_t)i * 64 + jj];
        s += h; s2 += h * h;
    }
    __shared__ float sh[64], sh2[64];
    if (tid < 64) { sh[tid] = 0.f; sh2[tid] = 0.f; }
    __syncthreads();
    atomicAdd(&sh[jj], s);
    atomicAdd(&sh2[jj], s2);
    __syncthreads();
    if (tid < 64) {
        atomicAdd(&g_bnsum[tid], sh[tid]);
        atomicAdd(&g_bnsq[tid],  sh2[tid]);
    }
}

// ---------------- K6: fold BN ------------------------------------------------
__global__ void k_bnscale(const float* __restrict__ gamma,
                          const float* __restrict__ beta) {
    int j = threadIdx.x;
    if (j >= DIM) return;
    float mean = g_bnsum[j] / (float)NPTS;
    float var  = g_bnsq[j] / (float)NPTS - mean * mean;
    float sc   = gamma[j] * rsqrtf(var + BN_EPS);
    g_scale[j] = sc;
    g_shift[j] = beta[j] - mean * sc;
}

// ---------------- K7: out ----------------------------------------------------
__global__ void k_out(const int* __restrict__ cluster, float* __restrict__ out) {
    int idx = blockIdx.x * blockDim.x + threadIdx.x;
    if (idx >= NPTS * 16) return;
    int i  = idx >> 4;
    int j4 = (idx & 15) * 4;
    float attn = g_e[i] * g_inv[cluster[i]];
    float4 v = *(const float4*)&g_v[(size_t)i * 64 + j4];
    float4 r;
    r.x = fmaxf(fmaf(attn * v.x, g_scale[j4 + 0], g_shift[j4 + 0]), 0.f);
    r.y = fmaxf(fmaf(attn * v.y, g_scale[j4 + 1], g_shift[j4 + 1]), 0.f);
    r.z = fmaxf(fmaf(attn * v.z, g_scale[j4 + 2], g_shift[j4 + 2]), 0.f);
    r.w = fmaxf(fmaf(attn * v.w, g_scale[j4 + 3], g_shift[j4 + 3]), 0.f);
    *(float4*)&out[(size_t)i * 64 + j4] = r;
}

// ---------------- launcher ---------------------------------------------------
extern "C" void kernel_launch(void* const* d_in, const int* in_sizes, int n_in,
                              void* d_out, int out_size) {
    (void)in_sizes; (void)n_in; (void)out_size;
    const float* x       = (const float*)d_in[1];
    const int*   cluster = (const int*)  d_in[2];
    const float* Wv      = (const float*)d_in[3];
    const float* bv      = (const float*)d_in[4];
    const float* Wk      = (const float*)d_in[5];
    const float* bk      = (const float*)d_in[6];
    const float* Wq      = (const float*)d_in[7];
    const float* bq      = (const float*)d_in[8];
    const float* gamma   = (const float*)d_in[9];
    const float* beta    = (const float*)d_in[10];
    float* out = (float*)d_out;

    k_init_qmax<<<(NC * DIM + 255) / 256, 256>>>();
    k_init_denom<<<(NC + 255) / 256, 256>>>();
    k_init_bn<<<1, 64>>>();

    size_t smem = (size_t)(64 * JS + TO + 2 * XSZ) * sizeof(float);
    cudaFuncSetAttribute(k_qv, cudaFuncAttributeMaxDynamicSharedMemorySize,
                         (int)smem);
    k_qv<<<444, 128, smem>>>(x, cluster, Wv, bv, Wq, bq);

    k_qtrans<<<NC / 4, 256>>>(Wk, bk);
    k_score<<<(NPTS * 8 + 255) / 256, 256>>>(x, cluster);
    k_invdenom<<<(NC + 255) / 256, 256>>>();
    k_bnstats<<<1184, 256>>>(cluster);
    k_bnscale<<<1, 64>>>(gamma, beta);
    k_out<<<(NPTS * 16 + 255) / 256, 256>>>(cluster, out);
}

// round 16
// speedup vs baseline: 1.0529x; 1.0529x over previous
#include <cuda_runtime.h>
#include <cuda_fp16.h>
#include <math.h>

#define NPTS 500000
#define DIM  64
#define NC   10000
#define TO   128            // 2*64 combined outputs (q|v)
#define BN_EPS 1e-5f

#define PS 68               // x_s row stride (floats)
#define JS 136              // w_s row stride (floats) — swizzled layout

typedef unsigned long long ull;

// ---------------- scratch (device globals: no allocation allowed) ------------
__device__ __half   g_v[(size_t)NPTS * DIM];     // 64 MB (fp16 v)
__device__ unsigned g_qmax[NC * DIM];            // order-encoded fp32 max
__device__ float    g_qw[NC * DIM];              // Wk^T q[c]
__device__ float    g_qb[NC];                    // q[c] . bk
__device__ float    g_denom[NC];
__device__ float    g_inv[NC];
__device__ float    g_e[NPTS];
__device__ float    g_bnsum[DIM];
__device__ float    g_bnsq[DIM];
__device__ float    g_scale[DIM];
__device__ float    g_shift[DIM];

__device__ __forceinline__ unsigned encf(float f) {
    unsigned u = __float_as_uint(f);
    return (u & 0x80000000u) ? ~u : (u | 0x80000000u);
}
__device__ __forceinline__ float decf(unsigned u) {
    return __uint_as_float((u & 0x80000000u) ? (u & 0x7FFFFFFFu) : ~u);
}
#define ENC_NEG_INF 0x007FFFFFu

// ---------------- packed fp32x2 helpers --------------------------------------
__device__ __forceinline__ ull pack_dup(float x) {
    ull r;
    asm("mov.b64 %0, {%1, %1};" : "=l"(r) : "f"(x));
    return r;
}
__device__ __forceinline__ void unpack2(ull p, float& lo, float& hi) {
    asm("mov.b64 {%0, %1}, %2;" : "=f"(lo), "=f"(hi) : "l"(p));
}
#define FMA_F32X2(d, a, b, c) \
    asm("fma.rn.f32x2 %0, %1, %2, %3;" : "=l"(d) : "l"(a), "l"(b), "l"(c))

// w_s column swizzle: conflict-free weight loads (16 distinct bank pairs)
__device__ __forceinline__ int jsw(int j) { return j + ((j >> 5) << 1); }

// ---------------- init kernels -----------------------------------------------
__global__ void k_init_qmax() {
    int i = blockIdx.x * blockDim.x + threadIdx.x;
    if (i < NC * DIM) g_qmax[i] = ENC_NEG_INF;
}
__global__ void k_init_denom() {
    int i = blockIdx.x * blockDim.x + threadIdx.x;
    if (i < NC) g_denom[i] = 0.f;
}
__global__ void k_init_bn() {
    int i = threadIdx.x;
    if (i < DIM) { g_bnsum[i] = 0.f; g_bnsq[i] = 0.f; }
}

// ---------------- K1: fused QV GEMM (f32x2) + filtered q seg-max + v fp16 ----
// R11 chassis (best measured): 128 thr, smem x staging, 8pt x 8col thread tile.
__global__ __launch_bounds__(128, 4)
void k_qv(const float* __restrict__ x, const int* __restrict__ cluster,
          const float* __restrict__ Wv, const float* __restrict__ bv,
          const float* __restrict__ Wq, const float* __restrict__ bq) {
    extern __shared__ float sm[];
    float* w_s = sm;                    // [64][JS]  swizzled (w_s[d][jsw(j)])
    float* x_s = sm + 64 * JS;          // [64][PS]
    float* b_s = x_s + 64 * PS;         // [128]
    __shared__ int c_s[2][64];

    const int tid = threadIdx.x;
    const int tx  = tid & 15;           // output-group 0..15
    const int ty  = tid >> 4;           // point-group 0..7
    const int j0  = tx * 8;
    const int p0  = ty * 8;
    const int jofs = j0 + ((tx >> 2) << 1);   // swizzled load base

    // weights transposed + biases (once per block)
    for (int l = tid; l < TO * 16; l += 128) {
        int j = l >> 4, dc = l & 15;
        const float* Wsrc = (j < 64) ? Wq : Wv;
        int jr = j & 63;
        float4 wv = *(const float4*)&Wsrc[jr * 64 + dc * 4];
        int js = jsw(j);
        w_s[(dc * 4 + 0) * JS + js] = wv.x;
        w_s[(dc * 4 + 1) * JS + js] = wv.y;
        w_s[(dc * 4 + 2) * JS + js] = wv.z;
        w_s[(dc * 4 + 3) * JS + js] = wv.w;
    }
    for (int l = tid; l < TO; l += 128)
        b_s[l] = (l < 64) ? bq[l] : bv[l - 64];
    __syncthreads();

    const int numTiles = (NPTS + 63) / 64;
    int buf = 0;
    for (int tile = blockIdx.x; tile < numTiles; tile += gridDim.x, buf ^= 1) {
        const int base = tile * 64;

        for (int l = tid; l < 64 * 16; l += 128) {
            int p = l >> 4, ch = l & 15;
            float4 xv = (base + p < NPTS)
                      ? *(const float4*)&x[(size_t)(base + p) * 64 + ch * 4]
                      : make_float4(0.f, 0.f, 0.f, 0.f);
            *(float4*)&x_s[p * PS + ch * 4] = xv;
        }
        if (tid < 64) c_s[buf][tid] = (base + tid < NPTS) ? cluster[base + tid] : 0;
        __syncthreads();

        ull acc[8][4];
        {
            const ull* bp = (const ull*)&b_s[j0];
            #pragma unroll
            for (int m = 0; m < 4; m++) {
                ull bb = bp[m];
                #pragma unroll
                for (int pp = 0; pp < 8; pp++) acc[pp][m] = bb;
            }
        }

        #pragma unroll 4
        for (int d4 = 0; d4 < 16; d4++) {
            float xr[8][4];
            #pragma unroll
            for (int pp = 0; pp < 8; pp++) {
                float4 t = *(const float4*)&x_s[(p0 + pp) * PS + d4 * 4];
                xr[pp][0] = t.x; xr[pp][1] = t.y; xr[pp][2] = t.z; xr[pp][3] = t.w;
            }
            #pragma unroll
            for (int q = 0; q < 4; q++) {
                const int d = d4 * 4 + q;
                const ull* wp = (const ull*)&w_s[d * JS + jofs];
                ull wr[4];
                #pragma unroll
                for (int m = 0; m < 4; m++) wr[m] = wp[m];
                #pragma unroll
                for (int pp = 0; pp < 8; pp++) {
                    ull a = pack_dup(xr[pp][q]);
                    #pragma unroll
                    for (int m = 0; m < 4; m++)
                        FMA_F32X2(acc[pp][m], a, wr[m], acc[pp][m]);
                }
            }
        }
        __syncthreads();

        if (tx < 8) {
            // q columns: filtered segment max (monotone => race-safe precheck)
            #pragma unroll
            for (int pp = 0; pp < 8; pp++) {
                const int p = p0 + pp;
                if (base + p < NPTS) {
                    const int cl = c_s[buf][p];
                    const uint4* gp = (const uint4*)&g_qmax[cl * 64 + j0];
                    uint4 c0 = __ldg(gp);
                    uint4 c1 = __ldg(gp + 1);
                    unsigned cur[8] = {c0.x, c0.y, c0.z, c0.w,
                                       c1.x, c1.y, c1.z, c1.w};
                    #pragma unroll
                    for (int m = 0; m < 4; m++) {
                        float lo, hi;
                        unpack2(acc[pp][m], lo, hi);
                        unsigned elo = encf(lo), ehi = encf(hi);
                        if (elo > cur[2 * m])
                            atomicMax(&g_qmax[cl * 64 + j0 + 2 * m], elo);
                        if (ehi > cur[2 * m + 1])
                            atomicMax(&g_qmax[cl * 64 + j0 + 2 * m + 1], ehi);
                    }
                }
            }
        } else {
            // v columns: fp16 pack, one 16B store per point (8 halfs)
            const int jv = j0 - 64;
            #pragma unroll
            for (int pp = 0; pp < 8; pp++) {
                const int p = p0 + pp;
                if (base + p < NPTS) {
                    float a0, a1, a2, a3, a4, a5, a6, a7;
                    unpack2(acc[pp][0], a0, a1);
                    unpack2(acc[pp][1], a2, a3);
                    unpack2(acc[pp][2], a4, a5);
                    unpack2(acc[pp][3], a6, a7);
                    __half2 h[4];
                    h[0] = __floats2half2_rn(a0, a1);
                    h[1] = __floats2half2_rn(a2, a3);
                    h[2] = __floats2half2_rn(a4, a5);
                    h[3] = __floats2half2_rn(a6, a7);
                    *(uint4*)&g_v[(size_t)(base + p) * 64 + jv] = *(const uint4*)h;
                }
            }
        }
    }
}

// ---------------- K2: qw[c] = Wk^T q[c], qb = q.bk ---------------------------
__global__ __launch_bounds__(256)
void k_qtrans(const float* __restrict__ Wk, const float* __restrict__ bk) {
    __shared__ float wks[64 * 64];
    __shared__ float qs[4][64];
    __shared__ float bks[64];
    const int tid = threadIdx.x;
    for (int l = tid; l < 64 * 64; l += 256) wks[l] = Wk[l];
    if (tid < 64) bks[tid] = bk[tid];
    const int cl = tid >> 6;
    const int d  = tid & 63;
    const int c  = blockIdx.x * 4 + cl;
    qs[cl][d] = decf(g_qmax[c * 64 + d]);
    __syncthreads();
    float s = 0.f;
    #pragma unroll 8
    for (int j = 0; j < 64; j++)
        s = fmaf(qs[cl][j], wks[j * 64 + d], s);
    g_qw[c * 64 + d] = s;
    if (d == 0) {
        float t = 0.f;
        #pragma unroll 8
        for (int j = 0; j < 64; j++) t = fmaf(qs[cl][j], bks[j], t);
        g_qb[c] = t;
    }
}

// ---------------- K3: fused score + exp + denom ------------------------------
__global__ void k_score(const float* __restrict__ x,
                        const int* __restrict__ cluster) {
    int t = blockIdx.x * blockDim.x + threadIdx.x;
    int i = t >> 3;
    int r = t & 7;
    if (i >= NPTS) return;
    int cl = cluster[i];
    const float4* xp = (const float4*)&x[(size_t)i * 64];
    const float4* qp = (const float4*)&g_qw[cl * 64];
    float s = 0.f;
    #pragma unroll
    for (int h = 0; h < 2; h++) {
        float4 xv = xp[r + h * 8];
        float4 qv = qp[r + h * 8];
        s += xv.x * qv.x + xv.y * qv.y + xv.z * qv.z + xv.w * qv.w;
    }
    s += __shfl_down_sync(0xFFFFFFFFu, s, 4);
    s += __shfl_down_sync(0xFFFFFFFFu, s, 2);
    s += __shfl_down_sync(0xFFFFFFFFu, s, 1);
    if (r == 0) {
        float e = expf(s + g_qb[cl]);
        g_e[i] = e;
        atomicAdd(&g_denom[cl], e);
    }
}

// ---------------- K4: inv ----------------------------------------------------
__global__ void k_invdenom() {
    int c = blockIdx.x * blockDim.x + threadIdx.x;
    if (c < NC) g_inv[c] = 1.0f / g_denom[c];
}

// ---------------- K5: BN statistics over h = attn * v (fp16 v) ---------------
__global__ void k_bnstats(const int* __restrict__ cluster) {
    const int tid = threadIdx.x;
    const int jj  = tid & 63;
    const int pg  = tid >> 6;
    float s = 0.f, s2 = 0.f;
    for (int i = blockIdx.x * 4 + pg; i < NPTS; i += gridDim.x * 4) {
        float attn = g_e[i] * g_inv[cluster[i]];
        float h = attn * __half2float(g_v[(size_t)i * 64 + jj]);
        s += h; s2 += h * h;
    }
    __shared__ float sh[64], sh2[64];
    if (tid < 64) { sh[tid] = 0.f; sh2[tid] = 0.f; }
    __syncthreads();
    atomicAdd(&sh[jj], s);
    atomicAdd(&sh2[jj], s2);
    __syncthreads();
    if (tid < 64) {
        atomicAdd(&g_bnsum[tid], sh[tid]);
        atomicAdd(&g_bnsq[tid],  sh2[tid]);
    }
}

// ---------------- K6: fold BN ------------------------------------------------
__global__ void k_bnscale(const float* __restrict__ gamma,
                          const float* __restrict__ beta) {
    int j = threadIdx.x;
    if (j >= DIM) return;
    float mean = g_bnsum[j] / (float)NPTS;
    float var  = g_bnsq[j] / (float)NPTS - mean * mean;
    float sc   = gamma[j] * rsqrtf(var + BN_EPS);
    g_scale[j] = sc;
    g_shift[j] = beta[j] - mean * sc;
}

// ---------------- K7: out = relu(h*scale + shift) (fp16 v in) ----------------
// One thread per 8 columns: 16B half load, 2x16B float stores, coalesced.
__global__ void k_out(const int* __restrict__ cluster, float* __restrict__ out) {
    int idx = blockIdx.x * blockDim.x + threadIdx.x;
    if (idx >= NPTS * 8) return;
    int i  = idx >> 3;
    int j8 = (idx & 7) * 8;
    float attn = g_e[i] * g_inv[cluster[i]];
    uint4 raw = *(const uint4*)&g_v[(size_t)i * 64 + j8];
    const __half2* hp = (const __half2*)&raw;
    float2 v01 = __half22float2(hp[0]);
    float2 v23 = __half22float2(hp[1]);
    float2 v45 = __half22float2(hp[2]);
    float2 v67 = __half22float2(hp[3]);
    float v[8] = {v01.x, v01.y, v23.x, v23.y, v45.x, v45.y, v67.x, v67.y};
    float4 r0, r1;
    r0.x = fmaxf(fmaf(attn * v[0], g_scale[j8 + 0], g_shift[j8 + 0]), 0.f);
    r0.y = fmaxf(fmaf(attn * v[1], g_scale[j8 + 1], g_shift[j8 + 1]), 0.f);
    r0.z = fmaxf(fmaf(attn * v[2], g_scale[j8 + 2], g_shift[j8 + 2]), 0.f);
    r0.w = fmaxf(fmaf(attn * v[3], g_scale[j8 + 3], g_shift[j8 + 3]), 0.f);
    r1.x = fmaxf(fmaf(attn * v[4], g_scale[j8 + 4], g_shift[j8 + 4]), 0.f);
    r1.y = fmaxf(fmaf(attn * v[5], g_scale[j8 + 5], g_shift[j8 + 5]), 0.f);
    r1.z = fmaxf(fmaf(attn * v[6], g_scale[j8 + 6], g_shift[j8 + 6]), 0.f);
    r1.w = fmaxf(fmaf(attn * v[7], g_scale[j8 + 7], g_shift[j8 + 7]), 0.f);
    float* dst = &out[(size_t)i * 64 + j8];
    *(float4*)dst       = r0;
    *(float4*)(dst + 4) = r1;
}

// ---------------- launcher ---------------------------------------------------
extern "C" void kernel_launch(void* const* d_in, const int* in_sizes, int n_in,
                              void* d_out, int out_size) {
    (void)in_sizes; (void)n_in; (void)out_size;
    const float* x       = (const float*)d_in[1];
    const int*   cluster = (const int*)  d_in[2];
    const float* Wv      = (const float*)d_in[3];
    const float* bv      = (const float*)d_in[4];
    const float* Wk      = (const float*)d_in[5];
    const float* bk      = (const float*)d_in[6];
    const float* Wq      = (const float*)d_in[7];
    const float* bq      = (const float*)d_in[8];
    const float* gamma   = (const float*)d_in[9];
    const float* beta    = (const float*)d_in[10];
    float* out = (float*)d_out;

    k_init_qmax<<<(NC * DIM + 255) / 256, 256>>>();
    k_init_denom<<<(NC + 255) / 256, 256>>>();
    k_init_bn<<<1, 64>>>();

    size_t smem = (size_t)(64 * JS + 64 * PS + TO) * sizeof(float);
    cudaFuncSetAttribute(k_qv, cudaFuncAttributeMaxDynamicSharedMemorySize,
                         (int)smem);
    k_qv<<<592, 128, smem>>>(x, cluster, Wv, bv, Wq, bq);

    k_qtrans<<<NC / 4, 256>>>(Wk, bk);
    k_score<<<(NPTS * 8 + 255) / 256, 256>>>(x, cluster);
    k_invdenom<<<(NC + 255) / 256, 256>>>();
    k_bnstats<<<1184, 256>>>(cluster);
    k_bnscale<<<1, 64>>>(gamma, beta);
    k_out<<<(NPTS * 8 + 255) / 256, 256>>>(cluster, out);
}

// round 17
// speedup vs baseline: 1.1298x; 1.0731x over previous
#include <cuda_runtime.h>
#include <cuda_fp16.h>
#include <math.h>

#define NPTS 500000
#define DIM  64
#define NC   10000
#define TO   128            // 2*64 combined outputs (q|v)
#define BN_EPS 1e-5f

#define PS 68               // x_s row stride (floats)
#define JS 136              // w_s row stride (floats) — swizzled layout
#define NUMTILES ((NPTS + 63) / 64)

typedef unsigned long long ull;

// ---------------- scratch (device globals: no allocation allowed) ------------
__device__ __half   g_v[(size_t)NPTS * DIM];     // 64 MB (fp16 v)
__device__ unsigned g_qmax[NC * DIM];            // order-encoded fp32 max
__device__ float    g_qw[NC * DIM];              // Wk^T q[c]
__device__ float    g_qb[NC];                    // q[c] . bk
__device__ float    g_denom[NC];
__device__ float    g_inv[NC];
__device__ float    g_e[NPTS];
__device__ float    g_bnsum[DIM];
__device__ float    g_bnsq[DIM];
__device__ float    g_scale[DIM];
__device__ float    g_shift[DIM];
__device__ int      g_tile_ctr;                  // work-stealing counter

__device__ __forceinline__ unsigned encf(float f) {
    unsigned u = __float_as_uint(f);
    return (u & 0x80000000u) ? ~u : (u | 0x80000000u);
}
__device__ __forceinline__ float decf(unsigned u) {
    return __uint_as_float((u & 0x80000000u) ? (u & 0x7FFFFFFFu) : ~u);
}
#define ENC_NEG_INF 0x007FFFFFu

// ---------------- packed fp32x2 helpers --------------------------------------
__device__ __forceinline__ ull pack_dup(float x) {
    ull r;
    asm("mov.b64 %0, {%1, %1};" : "=l"(r) : "f"(x));
    return r;
}
__device__ __forceinline__ void unpack2(ull p, float& lo, float& hi) {
    asm("mov.b64 {%0, %1}, %2;" : "=f"(lo), "=f"(hi) : "l"(p));
}
#define FMA_F32X2(d, a, b, c) \
    asm("fma.rn.f32x2 %0, %1, %2, %3;" : "=l"(d) : "l"(a), "l"(b), "l"(c))

// w_s column swizzle: conflict-free weight loads (16 distinct bank pairs)
__device__ __forceinline__ int jsw(int j) { return j + ((j >> 5) << 1); }

// ---------------- K0: merged init --------------------------------------------
__global__ void k_init() {
    int i = blockIdx.x * blockDim.x + threadIdx.x;
    if (i < NC * DIM) g_qmax[i] = ENC_NEG_INF;
    if (i < NC)       g_denom[i] = 0.f;
    if (i < DIM)      { g_bnsum[i] = 0.f; g_bnsq[i] = 0.f; }
    if (i == 0)       g_tile_ctr = 0;
}

// ---------------- K1: fused QV GEMM (f32x2) + filtered q seg-max + v fp16 ----
// R11 chassis + work-stealing tile loop (perfect load balance).
__global__ __launch_bounds__(128, 4)
void k_qv(const float* __restrict__ x, const int* __restrict__ cluster,
          const float* __restrict__ Wv, const float* __restrict__ bv,
          const float* __restrict__ Wq, const float* __restrict__ bq) {
    extern __shared__ float sm[];
    float* w_s = sm;                    // [64][JS]  swizzled (w_s[d][jsw(j)])
    float* x_s = sm + 64 * JS;          // [64][PS]
    float* b_s = x_s + 64 * PS;         // [128]
    __shared__ int c_s[2][64];
    __shared__ int tile_sh;

    const int tid = threadIdx.x;
    const int tx  = tid & 15;           // output-group 0..15
    const int ty  = tid >> 4;           // point-group 0..7
    const int j0  = tx * 8;
    const int p0  = ty * 8;
    const int jofs = j0 + ((tx >> 2) << 1);   // swizzled load base

    if (tid == 0) tile_sh = atomicAdd(&g_tile_ctr, 1);

    // weights transposed + biases (once per block)
    for (int l = tid; l < TO * 16; l += 128) {
        int j = l >> 4, dc = l & 15;
        const float* Wsrc = (j < 64) ? Wq : Wv;
        int jr = j & 63;
        float4 wv = *(const float4*)&Wsrc[jr * 64 + dc * 4];
        int js = jsw(j);
        w_s[(dc * 4 + 0) * JS + js] = wv.x;
        w_s[(dc * 4 + 1) * JS + js] = wv.y;
        w_s[(dc * 4 + 2) * JS + js] = wv.z;
        w_s[(dc * 4 + 3) * JS + js] = wv.w;
    }
    for (int l = tid; l < TO; l += 128)
        b_s[l] = (l < 64) ? bq[l] : bv[l - 64];
    __syncthreads();

    int tile = tile_sh;
    int buf = 0;
    while (tile < NUMTILES) {
        const int base = tile * 64;

        // stage x tile + cluster ids; tid0 concurrently fetches next tile
        for (int l = tid; l < 64 * 16; l += 128) {
            int p = l >> 4, ch = l & 15;
            float4 xv = (base + p < NPTS)
                      ? *(const float4*)&x[(size_t)(base + p) * 64 + ch * 4]
                      : make_float4(0.f, 0.f, 0.f, 0.f);
            *(float4*)&x_s[p * PS + ch * 4] = xv;
        }
        if (tid < 64) c_s[buf][tid] = (base + tid < NPTS) ? cluster[base + tid] : 0;
        if (tid == 0) tile_sh = atomicAdd(&g_tile_ctr, 1);
        __syncthreads();
        const int next = tile_sh;       // read before 2nd sync: safe vs next write

        ull acc[8][4];
        {
            const ull* bp = (const ull*)&b_s[j0];
            #pragma unroll
            for (int m = 0; m < 4; m++) {
                ull bb = bp[m];
                #pragma unroll
                for (int pp = 0; pp < 8; pp++) acc[pp][m] = bb;
            }
        }

        #pragma unroll 4
        for (int d4 = 0; d4 < 16; d4++) {
            float xr[8][4];
            #pragma unroll
            for (int pp = 0; pp < 8; pp++) {
                float4 t = *(const float4*)&x_s[(p0 + pp) * PS + d4 * 4];
                xr[pp][0] = t.x; xr[pp][1] = t.y; xr[pp][2] = t.z; xr[pp][3] = t.w;
            }
            #pragma unroll
            for (int q = 0; q < 4; q++) {
                const int d = d4 * 4 + q;
                const ull* wp = (const ull*)&w_s[d * JS + jofs];
                ull wr[4];
                #pragma unroll
                for (int m = 0; m < 4; m++) wr[m] = wp[m];
                #pragma unroll
                for (int pp = 0; pp < 8; pp++) {
                    ull a = pack_dup(xr[pp][q]);
                    #pragma unroll
                    for (int m = 0; m < 4; m++)
                        FMA_F32X2(acc[pp][m], a, wr[m], acc[pp][m]);
                }
            }
        }
        __syncthreads();   // x_s/c_s reads done; tile_sh may be rewritten next iter

        if (tx < 8) {
            // q columns: filtered segment max (monotone => race-safe precheck)
            #pragma unroll
            for (int pp = 0; pp < 8; pp++) {
                const int p = p0 + pp;
                if (base + p < NPTS) {
                    const int cl = c_s[buf][p];
                    const uint4* gp = (const uint4*)&g_qmax[cl * 64 + j0];
                    uint4 c0 = __ldg(gp);
                    uint4 c1 = __ldg(gp + 1);
                    unsigned cur[8] = {c0.x, c0.y, c0.z, c0.w,
                                       c1.x, c1.y, c1.z, c1.w};
                    #pragma unroll
                    for (int m = 0; m < 4; m++) {
                        float lo, hi;
                        unpack2(acc[pp][m], lo, hi);
                        unsigned elo = encf(lo), ehi = encf(hi);
                        if (elo > cur[2 * m])
                            atomicMax(&g_qmax[cl * 64 + j0 + 2 * m], elo);
                        if (ehi > cur[2 * m + 1])
                            atomicMax(&g_qmax[cl * 64 + j0 + 2 * m + 1], ehi);
                    }
                }
            }
        } else {
            // v columns: fp16 pack, one 16B store per point (8 halfs)
            const int jv = j0 - 64;
            #pragma unroll
            for (int pp = 0; pp < 8; pp++) {
                const int p = p0 + pp;
                if (base + p < NPTS) {
                    float a0, a1, a2, a3, a4, a5, a6, a7;
                    unpack2(acc[pp][0], a0, a1);
                    unpack2(acc[pp][1], a2, a3);
                    unpack2(acc[pp][2], a4, a5);
                    unpack2(acc[pp][3], a6, a7);
                    __half2 h[4];
                    h[0] = __floats2half2_rn(a0, a1);
                    h[1] = __floats2half2_rn(a2, a3);
                    h[2] = __floats2half2_rn(a4, a5);
                    h[3] = __floats2half2_rn(a6, a7);
                    *(uint4*)&g_v[(size_t)(base + p) * 64 + jv] = *(const uint4*)h;
                }
            }
        }
        tile = next;
        buf ^= 1;
    }
}

// ---------------- K2: qw[c] = Wk^T q[c], qb = q.bk ---------------------------
__global__ __launch_bounds__(256)
void k_qtrans(const float* __restrict__ Wk, const float* __restrict__ bk) {
    __shared__ float wks[64 * 64];
    __shared__ float qs[4][64];
    __shared__ float bks[64];
    const int tid = threadIdx.x;
    for (int l = tid; l < 64 * 64; l += 256) wks[l] = Wk[l];
    if (tid < 64) bks[tid] = bk[tid];
    const int cl = tid >> 6;
    const int d  = tid & 63;
    const int c  = blockIdx.x * 4 + cl;
    qs[cl][d] = decf(g_qmax[c * 64 + d]);
    __syncthreads();
    float s = 0.f;
    #pragma unroll 8
    for (int j = 0; j < 64; j++)
        s = fmaf(qs[cl][j], wks[j * 64 + d], s);
    g_qw[c * 64 + d] = s;
    if (d == 0) {
        float t = 0.f;
        #pragma unroll 8
        for (int j = 0; j < 64; j++) t = fmaf(qs[cl][j], bks[j], t);
        g_qb[c] = t;
    }
}

// ---------------- K3: fused score + exp + denom ------------------------------
__global__ void k_score(const float* __restrict__ x,
                        const int* __restrict__ cluster) {
    int t = blockIdx.x * blockDim.x + threadIdx.x;
    int i = t >> 3;
    int r = t & 7;
    if (i >= NPTS) return;
    int cl = cluster[i];
    const float4* xp = (const float4*)&x[(size_t)i * 64];
    const float4* qp = (const float4*)&g_qw[cl * 64];
    float s = 0.f;
    #pragma unroll
    for (int h = 0; h < 2; h++) {
        float4 xv = xp[r + h * 8];
        float4 qv = qp[r + h * 8];
        s += xv.x * qv.x + xv.y * qv.y + xv.z * qv.z + xv.w * qv.w;
    }
    s += __shfl_down_sync(0xFFFFFFFFu, s, 4);
    s += __shfl_down_sync(0xFFFFFFFFu, s, 2);
    s += __shfl_down_sync(0xFFFFFFFFu, s, 1);
    if (r == 0) {
        float e = expf(s + g_qb[cl]);
        g_e[i] = e;
        atomicAdd(&g_denom[cl], e);
    }
}

// ---------------- K4: inv ----------------------------------------------------
__global__ void k_invdenom() {
    int c = blockIdx.x * blockDim.x + threadIdx.x;
    if (c < NC) g_inv[c] = 1.0f / g_denom[c];
}

// ---------------- K5: BN statistics (half2 v, warp-uniform e/inv) ------------
__global__ void k_bnstats(const int* __restrict__ cluster) {
    const int tid = threadIdx.x;          // 256
    const int jp  = tid & 31;             // col-pair 0..31
    const int pg  = tid >> 5;             // point-group 0..7 (one warp each)
    float2 s  = make_float2(0.f, 0.f);
    float2 s2 = make_float2(0.f, 0.f);
    for (int i = blockIdx.x * 8 + pg; i < NPTS; i += gridDim.x * 8) {
        float attn = g_e[i] * g_inv[cluster[i]];
        __half2 hv = *(const __half2*)&g_v[(size_t)i * 64 + jp * 2];
        float2 v = __half22float2(hv);
        float h0 = attn * v.x, h1 = attn * v.y;
        s.x += h0; s.y += h1;
        s2.x += h0 * h0; s2.y += h1 * h1;
    }
    __shared__ float sh[64], sh2[64];
    if (tid < 64) { sh[tid] = 0.f; sh2[tid] = 0.f; }
    __syncthreads();
    atomicAdd(&sh[jp * 2],      s.x);
    atomicAdd(&sh[jp * 2 + 1],  s.y);
    atomicAdd(&sh2[jp * 2],     s2.x);
    atomicAdd(&sh2[jp * 2 + 1], s2.y);
    __syncthreads();
    if (tid < 64) {
        atomicAdd(&g_bnsum[tid], sh[tid]);
        atomicAdd(&g_bnsq[tid],  sh2[tid]);
    }
}

// ---------------- K6: fold BN ------------------------------------------------
__global__ void k_bnscale(const float* __restrict__ gamma,
                          const float* __restrict__ beta) {
    int j = threadIdx.x;
    if (j >= DIM) return;
    float mean = g_bnsum[j] / (float)NPTS;
    float var  = g_bnsq[j] / (float)NPTS - mean * mean;
    float sc   = gamma[j] * rsqrtf(var + BN_EPS);
    g_scale[j] = sc;
    g_shift[j] = beta[j] - mean * sc;
}

// ---------------- K7: out = relu(h*scale + shift) (fp16 v in) ----------------
__global__ void k_out(const int* __restrict__ cluster, float* __restrict__ out) {
    int idx = blockIdx.x * blockDim.x + threadIdx.x;
    if (idx >= NPTS * 8) return;
    int i  = idx >> 3;
    int j8 = (idx & 7) * 8;
    float attn = g_e[i] * g_inv[cluster[i]];
    uint4 raw = *(const uint4*)&g_v[(size_t)i * 64 + j8];
    const __half2* hp = (const __half2*)&raw;
    float2 v01 = __half22float2(hp[0]);
    float2 v23 = __half22float2(hp[1]);
    float2 v45 = __half22float2(hp[2]);
    float2 v67 = __half22float2(hp[3]);
    float v[8] = {v01.x, v01.y, v23.x, v23.y, v45.x, v45.y, v67.x, v67.y};
    float4 r0, r1;
    r0.x = fmaxf(fmaf(attn * v[0], g_scale[j8 + 0], g_shift[j8 + 0]), 0.f);
    r0.y = fmaxf(fmaf(attn * v[1], g_scale[j8 + 1], g_shift[j8 + 1]), 0.f);
    r0.z = fmaxf(fmaf(attn * v[2], g_scale[j8 + 2], g_shift[j8 + 2]), 0.f);
    r0.w = fmaxf(fmaf(attn * v[3], g_scale[j8 + 3], g_shift[j8 + 3]), 0.f);
    r1.x = fmaxf(fmaf(attn * v[4], g_scale[j8 + 4], g_shift[j8 + 4]), 0.f);
    r1.y = fmaxf(fmaf(attn * v[5], g_scale[j8 + 5], g_shift[j8 + 5]), 0.f);
    r1.z = fmaxf(fmaf(attn * v[6], g_scale[j8 + 6], g_shift[j8 + 6]), 0.f);
    r1.w = fmaxf(fmaf(attn * v[7], g_scale[j8 + 7], g_shift[j8 + 7]), 0.f);
    float* dst = &out[(size_t)i * 64 + j8];
    *(float4*)dst       = r0;
    *(float4*)(dst + 4) = r1;
}

// ---------------- launcher ---------------------------------------------------
extern "C" void kernel_launch(void* const* d_in, const int* in_sizes, int n_in,
                              void* d_out, int out_size) {
    (void)in_sizes; (void)n_in; (void)out_size;
    const float* x       = (const float*)d_in[1];
    const int*   cluster = (const int*)  d_in[2];
    const float* Wv      = (const float*)d_in[3];
    const float* bv      = (const float*)d_in[4];
    const float* Wk      = (const float*)d_in[5];
    const float* bk      = (const float*)d_in[6];
    const float* Wq      = (const float*)d_in[7];
    const float* bq      = (const float*)d_in[8];
    const float* gamma   = (const float*)d_in[9];
    const float* beta    = (const float*)d_in[10];
    float* out = (float*)d_out;

    k_init<<<(NC * DIM + 255) / 256, 256>>>();

    size_t smem = (size_t)(64 * JS + 64 * PS + TO) * sizeof(float);
    cudaFuncSetAttribute(k_qv, cudaFuncAttributeMaxDynamicSharedMemorySize,
                         (int)smem);
    k_qv<<<592, 128, smem>>>(x, cluster, Wv, bv, Wq, bq);

    k_qtrans<<<NC / 4, 256>>>(Wk, bk);
    k_score<<<(NPTS * 8 + 255) / 256, 256>>>(x, cluster);
    k_invdenom<<<(NC + 255) / 256, 256>>>();
    k_bnstats<<<592, 256>>>(cluster);
    k_bnscale<<<1, 64>>>(gamma, beta);
    k_out<<<(NPTS * 8 + 255) / 256, 256>>>(cluster, out);
}